// round 7
// baseline (speedup 1.0000x reference)
#include <cuda_runtime.h>
#include <math.h>
#include <stdint.h>

// ---------------- problem constants ----------------
#define BQ 4
#define LQ 1024
#define DMQ 512
#define DIQ 1024
#define NHQ 16
#define HDQ 64
#define NSQ 16
#define DCONVQ 4
#define CONV_DIMQ 1056
#define DPROJQ 2096
#define DFFQ 2048
#define NLAYERSQ 6
#define BLQ (BQ*LQ)          // 4096 rows
#define EPSQ 1e-5f

// GEMM tiling
#define BN 128
#define BK 32
#define LDK 36               // padded k-stride (floats); 144B = 9*16B -> ldmatrix-aligned, conflict-free

// scan chunking
#define NCHUNK 32
#define CLEN (LQ/NCHUNK)     // 32

// ---------------- scratch (device globals, no allocation) ----------------
__device__ float g_x  [BLQ*DMQ];
__device__ float g_xn [BLQ*DMQ];
__device__ float g_zx [BLQ*DPROJQ];
__device__ float g_xbc[BLQ*CONV_DIMQ];
__device__ float g_y  [BLQ*DIQ];
__device__ float g_h1 [BLQ*DFFQ];
__device__ float g_hfin [BQ*NHQ*NCHUNK*HDQ*NSQ];
__device__ float g_hinit[BQ*NHQ*NCHUNK*HDQ*NSQ];
__device__ float g_cuma [BLQ*NHQ];
__device__ float g_P    [BQ*NHQ*NCHUNK];
__device__ float g_wip[NLAYERSQ*DPROJQ*DMQ];
__device__ float g_wop[NLAYERSQ*DMQ*DIQ];
__device__ float g_w1 [NLAYERSQ*DFFQ*DMQ];
__device__ float g_w2 [NLAYERSQ*DMQ*DFFQ];

// ---------------- helpers ----------------
__device__ __forceinline__ float block_reduce_sum(float v, float* sh) {
    int lane = threadIdx.x & 31, wid = threadIdx.x >> 5;
    #pragma unroll
    for (int o = 16; o; o >>= 1) v += __shfl_xor_sync(0xFFFFFFFFu, v, o);
    if (lane == 0) sh[wid] = v;
    __syncthreads();
    int nw = blockDim.x >> 5;
    v = (threadIdx.x < nw) ? sh[threadIdx.x] : 0.f;
    if (wid == 0) {
        #pragma unroll
        for (int o = 16; o; o >>= 1) v += __shfl_xor_sync(0xFFFFFFFFu, v, o);
        if (lane == 0) sh[0] = v;
    }
    __syncthreads();
    float r = sh[0];
    __syncthreads();
    return r;
}

__device__ __forceinline__ uint32_t f2tf32(float f) {
    uint32_t u;
    asm("cvt.rna.tf32.f32 %0, %1;" : "=r"(u) : "f"(f));
    return u;
}
__device__ __forceinline__ float rnd_tf32(float f) { return __uint_as_float(f2tf32(f)); }

__device__ __forceinline__ void cp16(uint32_t dst, const void* src, bool pred) {
    int sz = pred ? 16 : 0;
    asm volatile("cp.async.cg.shared.global [%0], [%1], 16, %2;\n"
                 :: "r"(dst), "l"(src), "r"(sz) : "memory");
}
__device__ __forceinline__ void cp_commit() {
    asm volatile("cp.async.commit_group;\n" ::: "memory");
}

__device__ __forceinline__ void ldsm4(uint32_t& r0, uint32_t& r1, uint32_t& r2, uint32_t& r3,
                                      uint32_t addr) {
    asm volatile("ldmatrix.sync.aligned.m8n8.x4.shared.b16 {%0,%1,%2,%3}, [%4];"
                 : "=r"(r0), "=r"(r1), "=r"(r2), "=r"(r3) : "r"(addr));
}

__global__ void cvt_tf32_kernel(const float* __restrict__ in, float* __restrict__ out, int n) {
    int i = (blockIdx.x * blockDim.x + threadIdx.x) * 4;
    if (i < n) {
        float4 v = *(const float4*)&in[i];
        v.x = rnd_tf32(v.x); v.y = rnd_tf32(v.y);
        v.z = rnd_tf32(v.z); v.w = rnd_tf32(v.w);
        *(float4*)&out[i] = v;
    }
}

// ---------------- rmsnorm over DM=512 ----------------
// COPY=1: also copy the raw input row into xcopy (fuses the initial residual copy)
template<int COPY>
__global__ void rmsnorm_kernel(const float* __restrict__ in, const float* __restrict__ w,
                               float* __restrict__ out, float* __restrict__ xcopy,
                               int round_out) {
    __shared__ float sh[32];
    int m = blockIdx.x;
    int t = threadIdx.x;
    const float* row = in + (size_t)m * DMQ;
    float v[4]; float ss = 0.f;
    #pragma unroll
    for (int i = 0; i < 4; i++) { v[i] = row[t + i*128]; ss += v[i]*v[i]; }
    float tot = block_reduce_sum(ss, sh);
    float scale = rsqrtf(tot * (1.f/DMQ) + EPSQ);
    float* orow = out + (size_t)m * DMQ;
    #pragma unroll
    for (int i = 0; i < 4; i++) {
        float o = v[i] * scale * w[t + i*128];
        orow[t + i*128] = round_out ? rnd_tf32(o) : o;
        if (COPY) xcopy[(size_t)m * DMQ + t + i*128] = v[i];
    }
}

// ---------------- tensor-core GEMM: C[M,N] = A[M,K] @ W[N,K]^T (+ epilogue) ----------------
// tf32 mma.sync m16n8k8, cp.async double-buffered, ldmatrix fragment loads.
// 256 threads = 8 warps (2x4), warp tile (BMt/2) x 32.
// EPI: 0 = plain, 1 = bias+gelu(exact, round out), 2 = +resid, 3 = bias+resid
template<int EPI, int BMt>
__global__ void __launch_bounds__(256, (BMt==128) ? 2 : 3)
gemm_tc5(const float* __restrict__ A, const float* __restrict__ W,
         float* __restrict__ C, const float* __restrict__ bias,
         const float* __restrict__ resid, int M, int N, int K) {
    constexpr int MT = BMt / 32;           // m16 tiles per warp (4 or 2)
    extern __shared__ float sm[];
    float* As = sm;                        // [2][BMt][LDK]
    float* Bs = sm + 2 * BMt * LDK;        // [2][BN][LDK]

    int tid  = threadIdx.x;
    int warp = tid >> 5, lane = tid & 31;
    int wm = warp & 1;                     // row half
    int wn = warp >> 1;                    // 0..3, 32-col slab

    int m0 = blockIdx.y * BMt;
    int n0 = blockIdx.x * BN;

    float acc[MT][4][4];
    #pragma unroll
    for (int i = 0; i < MT; i++)
        #pragma unroll
        for (int j = 0; j < 4; j++)
            #pragma unroll
            for (int c = 0; c < 4; c++) acc[i][j][c] = 0.f;

    auto stage = [&](int buf, int k0) {
        float* Ab = As + buf * BMt * LDK;
        #pragma unroll
        for (int it = 0; it < (BMt*8)/256; it++) {
            int ch = it * 256 + tid;
            int r = ch >> 3, kc = (ch & 7) * 4;
            uint32_t dst = (uint32_t)__cvta_generic_to_shared(&Ab[r * LDK + kc]);
            cp16(dst, &A[(size_t)(m0 + r) * K + k0 + kc], true);
        }
        float* Bb = Bs + buf * BN * LDK;
        #pragma unroll
        for (int it = 0; it < 4; it++) {
            int ch = it * 256 + tid;
            int r = ch >> 3, kc = (ch & 7) * 4;
            int n = n0 + r;
            bool ok = (n < N);
            uint32_t dst = (uint32_t)__cvta_generic_to_shared(&Bb[r * LDK + kc]);
            cp16(dst, &W[(size_t)(ok ? n : 0) * K + k0 + kc], ok);
        }
        cp_commit();
    };

    // ldmatrix per-lane base offsets (bytes, relative to tile base)
    uint32_t aRow = (uint32_t)(wm * (BMt/2) + (lane & 15));
    uint32_t aColB = (lane >> 4) * 16;
    uint32_t aBaseOff = (aRow * LDK) * 4 + aColB;
    uint32_t bRow = (uint32_t)(wn * 32 + (lane & 7) + ((lane & 16) >> 1));
    uint32_t bColB = (lane & 8) * 2;
    uint32_t bBaseOff = (bRow * LDK) * 4 + bColB;

    int ntiles = K / BK;
    stage(0, 0);
    for (int i = 0; i < ntiles; i++) {
        if (i + 1 < ntiles) {
            stage((i + 1) & 1, (i + 1) * BK);
            asm volatile("cp.async.wait_group 1;\n" ::: "memory");
        } else {
            asm volatile("cp.async.wait_group 0;\n" ::: "memory");
        }
        __syncthreads();

        uint32_t sAb = (uint32_t)__cvta_generic_to_shared(As + (i & 1) * BMt * LDK);
        uint32_t sBb = (uint32_t)__cvta_generic_to_shared(Bs + (i & 1) * BN * LDK);
        uint32_t aAddr = sAb + aBaseOff;
        uint32_t bAddr = sBb + bBaseOff;

        #pragma unroll
        for (int kk = 0; kk < BK; kk += 8) {
            uint32_t af[MT][4];
            #pragma unroll
            for (int mt = 0; mt < MT; mt++)
                ldsm4(af[mt][0], af[mt][1], af[mt][2], af[mt][3],
                      aAddr + (uint32_t)(mt * 16 * LDK + kk) * 4);
            uint32_t bf[4][2];
            #pragma unroll
            for (int ntp = 0; ntp < 2; ntp++)
                ldsm4(bf[2*ntp][0], bf[2*ntp][1], bf[2*ntp+1][0], bf[2*ntp+1][1],
                      bAddr + (uint32_t)(ntp * 16 * LDK + kk) * 4);
            #pragma unroll
            for (int mt = 0; mt < MT; mt++)
                #pragma unroll
                for (int nt = 0; nt < 4; nt++) {
                    asm volatile(
                        "mma.sync.aligned.m16n8k8.row.col.f32.tf32.tf32.f32 "
                        "{%0,%1,%2,%3}, {%4,%5,%6,%7}, {%8,%9}, {%0,%1,%2,%3};"
                        : "+f"(acc[mt][nt][0]), "+f"(acc[mt][nt][1]),
                          "+f"(acc[mt][nt][2]), "+f"(acc[mt][nt][3])
                        : "r"(af[mt][0]), "r"(af[mt][1]), "r"(af[mt][2]), "r"(af[mt][3]),
                          "r"(bf[nt][0]), "r"(bf[nt][1]));
                }
        }
        __syncthreads();
    }

    // epilogue: float2 stores
    int gg = lane >> 2, tt = lane & 3;
    #pragma unroll
    for (int mt = 0; mt < MT; mt++) {
        #pragma unroll
        for (int nt = 0; nt < 4; nt++) {
            int mbase = m0 + wm * (BMt/2) + mt * 16 + gg;
            int nn = n0 + wn * 32 + nt * 8 + 2 * tt;
            if (nn < N) {
                #pragma unroll
                for (int rhalf = 0; rhalf < 2; rhalf++) {
                    int mm = mbase + rhalf * 8;
                    float v0 = acc[mt][nt][rhalf*2 + 0];
                    float v1 = acc[mt][nt][rhalf*2 + 1];
                    if (EPI == 1) {
                        v0 += bias[nn];     v1 += bias[nn+1];
                        v0 = 0.5f * v0 * (1.f + erff(v0 * 0.70710678118654752f));
                        v1 = 0.5f * v1 * (1.f + erff(v1 * 0.70710678118654752f));
                        v0 = rnd_tf32(v0);  v1 = rnd_tf32(v1);
                    } else if (EPI == 2) {
                        float2 r = *(const float2*)&resid[(size_t)mm * N + nn];
                        v0 += r.x; v1 += r.y;
                    } else if (EPI == 3) {
                        float2 r = *(const float2*)&resid[(size_t)mm * N + nn];
                        v0 += bias[nn] + r.x; v1 += bias[nn+1] + r.y;
                    }
                    *(float2*)&C[(size_t)mm * N + nn] = make_float2(v0, v1);
                }
            }
        }
    }
}

// ---------------- causal depthwise conv (k=4) + bias + silu ----------------
__global__ void conv_kernel(const float* __restrict__ zx, const float* __restrict__ cw,
                            const float* __restrict__ cb, float* __restrict__ out) {
    int idx = blockIdx.x * blockDim.x + threadIdx.x;
    if (idx >= BLQ*CONV_DIMQ) return;
    int m = idx / CONV_DIMQ;
    int c = idx % CONV_DIMQ;
    int b = m / LQ, l = m % LQ;
    float acc = cb[c];
    #pragma unroll
    for (int j = 0; j < DCONVQ; j++) {
        int ll = l - (DCONVQ-1) + j;
        if (ll >= 0)
            acc += zx[(size_t)(b*LQ + ll)*DPROJQ + DIQ + c] * cw[c*DCONVQ + j];
    }
    out[idx] = acc / (1.f + expf(-acc));
}

// ---------------- chunked scan pass 1 (dt/dA computed inline) ----------------
__global__ void scan1_kernel(const float* __restrict__ xbc, const float* __restrict__ zx,
                             const float* __restrict__ dtb, const float* __restrict__ Alog,
                             const float* __restrict__ D_ssm,
                             float* __restrict__ y, float* __restrict__ hfin,
                             float* __restrict__ cuma, float* __restrict__ P) {
    int blk = blockIdx.x;
    int c = blk % NCHUNK;
    int bh = blk / NCHUNK;
    int h = bh % NHQ, b = bh / NHQ;
    int p = threadIdx.x;
    int lane = p & 31;
    float Dh = D_ssm[h];
    float dtbh = dtb[h];
    float eA = expf(Alog[h]);
    float hs[NSQ];
    #pragma unroll
    for (int n = 0; n < NSQ; n++) hs[n] = 0.f;
    float cum = 1.f;
    int l0 = c * CLEN;

    for (int l = l0; l < l0 + CLEN; l++) {
        size_t row = (size_t)b * LQ + l;
        float bcv = xbc[row*CONV_DIMQ + DIQ + lane];
        float xv  = xbc[row*CONV_DIMQ + h*HDQ + p];
        float raw = zx[row*DPROJQ + (DPROJQ - NHQ) + h] + dtbh;   // broadcast load
        float dtv = (raw > 20.f) ? raw : log1pf(expf(raw));
        float a   = expf(-eA * dtv);
        cum *= a;
        if (p == 0) cuma[row*NHQ + h] = cum;
        float coef = dtv * xv;
        float acc = 0.f;
        #pragma unroll
        for (int n = 0; n < NSQ; n++) {
            float Bn = __shfl_sync(0xFFFFFFFFu, bcv, n);
            float Cn = __shfl_sync(0xFFFFFFFFu, bcv, 16 + n);
            hs[n] = fmaf(hs[n], a, coef * Bn);
            acc = fmaf(hs[n], Cn, acc);
        }
        y[row*DIQ + h*HDQ + p] = acc + Dh * xv;
    }
    size_t base = ((size_t)blk * HDQ + p) * NSQ;
    #pragma unroll
    for (int n = 0; n < NSQ; n++) hfin[base + n] = hs[n];
    if (p == 0) P[blk] = cum;
}

// ---------------- chunked scan pass 2 ----------------
__global__ void scan2_kernel(const float* __restrict__ hfin, const float* __restrict__ P,
                             float* __restrict__ hinit) {
    int bh = blockIdx.x;
    for (int e = threadIdx.x; e < HDQ*NSQ; e += 256) {
        float cur = 0.f;
        #pragma unroll 4
        for (int cc = 0; cc < NCHUNK; cc++) {
            size_t idx = (size_t)(bh * NCHUNK + cc) * (HDQ*NSQ) + e;
            hinit[idx] = cur;
            cur = P[bh * NCHUNK + cc] * cur + hfin[idx];
        }
    }
}

// ---------------- chunked scan pass 3 ----------------
__global__ void scan3_kernel(const float* __restrict__ xbc, const float* __restrict__ cuma,
                             const float* __restrict__ hinit, float* __restrict__ y) {
    int blk = blockIdx.x;
    int c = blk % NCHUNK;
    if (c == 0) return;
    int bh = blk / NCHUNK;
    int h = bh % NHQ, b = bh / NHQ;
    int p = threadIdx.x;
    int lane = p & 31;
    float hi[NSQ];
    size_t base = ((size_t)blk * HDQ + p) * NSQ;
    #pragma unroll
    for (int n = 0; n < NSQ; n++) hi[n] = hinit[base + n];
    int l0 = c * CLEN;
    for (int l = l0; l < l0 + CLEN; l++) {
        size_t row = (size_t)b * LQ + l;
        float bcv = xbc[row*CONV_DIMQ + DIQ + lane];
        float ca  = cuma[row*NHQ + h];
        float corr = 0.f;
        #pragma unroll
        for (int n = 0; n < NSQ; n++)
            corr = fmaf(hi[n], __shfl_sync(0xFFFFFFFFu, bcv, 16 + n), corr);
        y[row*DIQ + h*HDQ + p] += ca * corr;
    }
}

// ---------------- gated RMSNorm over DI=1024 ----------------
__global__ void gate_norm_kernel(float* __restrict__ y, const float* __restrict__ zx,
                                 const float* __restrict__ gw) {
    __shared__ float sh[32];
    int m = blockIdx.x;
    int t = threadIdx.x;
    float v[4]; float ss = 0.f;
    #pragma unroll
    for (int i = 0; i < 4; i++) {
        int c = t + i*256;
        float z = zx[(size_t)m*DPROJQ + c];
        float yy = y[(size_t)m*DIQ + c];
        float g = z / (1.f + expf(-z));
        v[i] = yy * g;
        ss += v[i]*v[i];
    }
    float tot = block_reduce_sum(ss, sh);
    float scale = rsqrtf(tot * (1.f/DIQ) + EPSQ);
    #pragma unroll
    for (int i = 0; i < 4; i++) {
        int c = t + i*256;
        y[(size_t)m*DIQ + c] = rnd_tf32(v[i] * scale * gw[c]);
    }
}

// ---------------- launcher ----------------
extern "C" void kernel_launch(void* const* d_in, const int* in_sizes, int n_in,
                              void* d_out, int out_size) {
    const float* x          = (const float*)d_in[0];
    const float* in_proj_w  = (const float*)d_in[1];
    const float* conv_w     = (const float*)d_in[2];
    const float* conv_b     = (const float*)d_in[3];
    const float* dt_bias    = (const float*)d_in[4];
    const float* A_log      = (const float*)d_in[5];
    const float* D_ssm      = (const float*)d_in[6];
    const float* gnorm_w    = (const float*)d_in[7];
    const float* out_proj_w = (const float*)d_in[8];
    const float* ffn_w1     = (const float*)d_in[9];
    const float* ffn_b1     = (const float*)d_in[10];
    const float* ffn_w2     = (const float*)d_in[11];
    const float* ffn_b2     = (const float*)d_in[12];
    const float* norm_mamba = (const float*)d_in[13];
    const float* norm_ffn   = (const float*)d_in[14];
    const float* final_norm = (const float*)d_in[15];
    float* out = (float*)d_out;

    float *gx, *gxn, *gzx, *gxbc, *gy, *gh1;
    float *ghfin, *ghinit, *gcuma, *gP, *gwip, *gwop, *gw1, *gw2;
    cudaGetSymbolAddress((void**)&gx,  g_x);
    cudaGetSymbolAddress((void**)&gxn, g_xn);
    cudaGetSymbolAddress((void**)&gzx, g_zx);
    cudaGetSymbolAddress((void**)&gxbc,g_xbc);
    cudaGetSymbolAddress((void**)&gy,  g_y);
    cudaGetSymbolAddress((void**)&gh1, g_h1);
    cudaGetSymbolAddress((void**)&ghfin, g_hfin);
    cudaGetSymbolAddress((void**)&ghinit,g_hinit);
    cudaGetSymbolAddress((void**)&gcuma, g_cuma);
    cudaGetSymbolAddress((void**)&gP,    g_P);
    cudaGetSymbolAddress((void**)&gwip,  g_wip);
    cudaGetSymbolAddress((void**)&gwop,  g_wop);
    cudaGetSymbolAddress((void**)&gw1,   g_w1);
    cudaGetSymbolAddress((void**)&gw2,   g_w2);

    const int smem128 = (2*128*LDK + 2*BN*LDK) * 4;
    const int smem64  = (2*64 *LDK + 2*BN*LDK) * 4;
    cudaFuncSetAttribute(gemm_tc5<0,128>, cudaFuncAttributeMaxDynamicSharedMemorySize, smem128);
    cudaFuncSetAttribute(gemm_tc5<1,128>, cudaFuncAttributeMaxDynamicSharedMemorySize, smem128);
    cudaFuncSetAttribute(gemm_tc5<2,64>,  cudaFuncAttributeMaxDynamicSharedMemorySize, smem64);
    cudaFuncSetAttribute(gemm_tc5<3,64>,  cudaFuncAttributeMaxDynamicSharedMemorySize, smem64);

    // pre-round all weights to tf32 bit patterns (launches 0-3)
    {
        int n;
        n = NLAYERSQ*DPROJQ*DMQ; cvt_tf32_kernel<<<(n/4+255)/256, 256>>>(in_proj_w,  gwip, n);
        n = NLAYERSQ*DMQ*DIQ;    cvt_tf32_kernel<<<(n/4+255)/256, 256>>>(out_proj_w, gwop, n);
        n = NLAYERSQ*DFFQ*DMQ;   cvt_tf32_kernel<<<(n/4+255)/256, 256>>>(ffn_w1,     gw1, n);
        n = NLAYERSQ*DMQ*DFFQ;   cvt_tf32_kernel<<<(n/4+255)/256, 256>>>(ffn_w2,     gw2, n);
    }

    for (int i = 0; i < NLAYERSQ; i++) {
        // --- mamba block ---
        if (i == 0) {
            // layer-0: read the harness input directly, fuse the residual copy (launch 4)
            rmsnorm_kernel<1><<<BLQ, 128>>>(x, norm_mamba, gxn, gx, 1);
        } else {
            rmsnorm_kernel<0><<<BLQ, 128>>>(gx, norm_mamba + i*DMQ, gxn, nullptr, 1);
        }

        // launch 5 on layer 0: the dominant GEMM -> gets profiled
        gemm_tc5<0,128><<<dim3((DPROJQ+BN-1)/BN, BLQ/128), 256, smem128>>>(
            gxn, gwip + (size_t)i*DPROJQ*DMQ, gzx, nullptr, nullptr,
            BLQ, DPROJQ, DMQ);

        conv_kernel<<<(BLQ*CONV_DIMQ + 255)/256, 256>>>(
            gzx, conv_w + (size_t)i*CONV_DIMQ*DCONVQ, conv_b + (size_t)i*CONV_DIMQ, gxbc);

        scan1_kernel<<<BQ*NHQ*NCHUNK, HDQ>>>(gxbc, gzx, dt_bias + i*NHQ, A_log + i*NHQ,
                                             D_ssm + i*NHQ, gy, ghfin, gcuma, gP);
        scan2_kernel<<<BQ*NHQ, 256>>>(ghfin, gP, ghinit);
        scan3_kernel<<<BQ*NHQ*NCHUNK, HDQ>>>(gxbc, gcuma, ghinit, gy);

        gate_norm_kernel<<<BLQ, 256>>>(gy, gzx, gnorm_w + (size_t)i*DIQ);

        gemm_tc5<2,64><<<dim3(DMQ/BN, BLQ/64), 256, smem64>>>(
            gy, gwop + (size_t)i*DMQ*DIQ, gx, nullptr, gx,
            BLQ, DMQ, DIQ);

        // --- ffn block ---
        rmsnorm_kernel<0><<<BLQ, 128>>>(gx, norm_ffn + i*DMQ, gxn, nullptr, 1);

        gemm_tc5<1,128><<<dim3(DFFQ/BN, BLQ/128), 256, smem128>>>(
            gxn, gw1 + (size_t)i*DFFQ*DMQ, gh1, ffn_b1 + (size_t)i*DFFQ, nullptr,
            BLQ, DFFQ, DMQ);

        gemm_tc5<3,64><<<dim3(DMQ/BN, BLQ/64), 256, smem64>>>(
            gh1, gw2 + (size_t)i*DMQ*DFFQ, gx, ffn_b2 + (size_t)i*DMQ, gx,
            BLQ, DMQ, DFFQ);
    }

    rmsnorm_kernel<0><<<BLQ, 128>>>(gx, final_norm, out, nullptr, 0);
}

// round 8
// speedup vs baseline: 1.0161x; 1.0161x over previous
#include <cuda_runtime.h>
#include <math.h>
#include <stdint.h>

// ---------------- problem constants ----------------
#define BQ 4
#define LQ 1024
#define DMQ 512
#define DIQ 1024
#define NHQ 16
#define HDQ 64
#define NSQ 16
#define DCONVQ 4
#define CONV_DIMQ 1056
#define DPROJQ 2096
#define DFFQ 2048
#define NLAYERSQ 6
#define BLQ (BQ*LQ)          // 4096 rows
#define EPSQ 1e-5f

// GEMM tiling
#define BN 128
#define BK 32
#define LDK 36               // padded k-stride (floats); 144B = 9*16B -> ldmatrix-aligned, conflict-free

// scan chunking
#define NCHUNK 32
#define CLEN (LQ/NCHUNK)     // 32

// ---------------- scratch (device globals, no allocation) ----------------
__device__ float g_x  [BLQ*DMQ];
__device__ float g_xn [BLQ*DMQ];
__device__ float g_zx [BLQ*DPROJQ];
__device__ float g_bc [BLQ*2*NSQ];       // conv+silu'd B,C (compact)
__device__ float g_y  [BLQ*DIQ];
__device__ float g_h1 [BLQ*DFFQ];
__device__ float g_hfin [BQ*NHQ*NCHUNK*HDQ*NSQ];
__device__ float g_hinit[BQ*NHQ*NCHUNK*HDQ*NSQ];
__device__ float g_cuma [BLQ*NHQ];
__device__ float g_P    [BQ*NHQ*NCHUNK];
__device__ float g_wip[NLAYERSQ*DPROJQ*DMQ];
__device__ float g_wop[NLAYERSQ*DMQ*DIQ];
__device__ float g_w1 [NLAYERSQ*DFFQ*DMQ];
__device__ float g_w2 [NLAYERSQ*DMQ*DFFQ];

// ---------------- helpers ----------------
__device__ __forceinline__ float block_reduce_sum(float v, float* sh) {
    int lane = threadIdx.x & 31, wid = threadIdx.x >> 5;
    #pragma unroll
    for (int o = 16; o; o >>= 1) v += __shfl_xor_sync(0xFFFFFFFFu, v, o);
    if (lane == 0) sh[wid] = v;
    __syncthreads();
    int nw = blockDim.x >> 5;
    v = (threadIdx.x < nw) ? sh[threadIdx.x] : 0.f;
    if (wid == 0) {
        #pragma unroll
        for (int o = 16; o; o >>= 1) v += __shfl_xor_sync(0xFFFFFFFFu, v, o);
        if (lane == 0) sh[0] = v;
    }
    __syncthreads();
    float r = sh[0];
    __syncthreads();
    return r;
}

__device__ __forceinline__ uint32_t f2tf32(float f) {
    uint32_t u;
    asm("cvt.rna.tf32.f32 %0, %1;" : "=r"(u) : "f"(f));
    return u;
}
__device__ __forceinline__ float rnd_tf32(float f) { return __uint_as_float(f2tf32(f)); }

__device__ __forceinline__ void cp16(uint32_t dst, const void* src, bool pred) {
    int sz = pred ? 16 : 0;
    asm volatile("cp.async.cg.shared.global [%0], [%1], 16, %2;\n"
                 :: "r"(dst), "l"(src), "r"(sz) : "memory");
}
__device__ __forceinline__ void cp_commit() {
    asm volatile("cp.async.commit_group;\n" ::: "memory");
}

__device__ __forceinline__ void ldsm4(uint32_t& r0, uint32_t& r1, uint32_t& r2, uint32_t& r3,
                                      uint32_t addr) {
    asm volatile("ldmatrix.sync.aligned.m8n8.x4.shared.b16 {%0,%1,%2,%3}, [%4];"
                 : "=r"(r0), "=r"(r1), "=r"(r2), "=r"(r3) : "r"(addr));
}

__global__ void cvt_tf32_kernel(const float* __restrict__ in, float* __restrict__ out, int n) {
    int i = (blockIdx.x * blockDim.x + threadIdx.x) * 4;
    if (i < n) {
        float4 v = *(const float4*)&in[i];
        v.x = rnd_tf32(v.x); v.y = rnd_tf32(v.y);
        v.z = rnd_tf32(v.z); v.w = rnd_tf32(v.w);
        *(float4*)&out[i] = v;
    }
}

// ---------------- rmsnorm over DM=512 ----------------
template<int COPY>
__global__ void rmsnorm_kernel(const float* __restrict__ in, const float* __restrict__ w,
                               float* __restrict__ out, float* __restrict__ xcopy,
                               int round_out) {
    __shared__ float sh[32];
    int m = blockIdx.x;
    int t = threadIdx.x;
    const float* row = in + (size_t)m * DMQ;
    float v[4]; float ss = 0.f;
    #pragma unroll
    for (int i = 0; i < 4; i++) { v[i] = row[t + i*128]; ss += v[i]*v[i]; }
    float tot = block_reduce_sum(ss, sh);
    float scale = rsqrtf(tot * (1.f/DMQ) + EPSQ);
    float* orow = out + (size_t)m * DMQ;
    #pragma unroll
    for (int i = 0; i < 4; i++) {
        float o = v[i] * scale * w[t + i*128];
        orow[t + i*128] = round_out ? rnd_tf32(o) : o;
        if (COPY) xcopy[(size_t)m * DMQ + t + i*128] = v[i];
    }
}

// ---------------- tensor-core GEMM: C[M,N] = A[M,K] @ W[N,K]^T (+ epilogue) ----------------
// tf32 mma.sync m16n8k8, cp.async double-buffered, ldmatrix fragment loads.
// 128 threads = 4 warps (2x2), warp tile (BMt/2) x 64.   (best measured config, R5)
// EPI: 0 = plain, 1 = bias+gelu(exact, round out), 2 = +resid, 3 = bias+resid
template<int EPI, int BMt>
__global__ void __launch_bounds__(128, (BMt==128) ? 2 : 3)
gemm_tc4(const float* __restrict__ A, const float* __restrict__ W,
         float* __restrict__ C, const float* __restrict__ bias,
         const float* __restrict__ resid, int M, int N, int K) {
    constexpr int MT = BMt / 32;
    extern __shared__ float sm[];
    float* As = sm;                        // [2][BMt][LDK]
    float* Bs = sm + 2 * BMt * LDK;        // [2][BN][LDK]

    int tid  = threadIdx.x;
    int warp = tid >> 5, lane = tid & 31;
    int wm = warp & 1;
    int wn = warp >> 1;

    int m0 = blockIdx.y * BMt;
    int n0 = blockIdx.x * BN;

    float acc[MT][8][4];
    #pragma unroll
    for (int i = 0; i < MT; i++)
        #pragma unroll
        for (int j = 0; j < 8; j++)
            #pragma unroll
            for (int c = 0; c < 4; c++) acc[i][j][c] = 0.f;

    auto stage = [&](int buf, int k0) {
        float* Ab = As + buf * BMt * LDK;
        #pragma unroll
        for (int it = 0; it < (BMt*8)/128; it++) {
            int ch = it * 128 + tid;
            int r = ch >> 3, kc = (ch & 7) * 4;
            uint32_t dst = (uint32_t)__cvta_generic_to_shared(&Ab[r * LDK + kc]);
            cp16(dst, &A[(size_t)(m0 + r) * K + k0 + kc], true);
        }
        float* Bb = Bs + buf * BN * LDK;
        #pragma unroll
        for (int it = 0; it < 8; it++) {
            int ch = it * 128 + tid;
            int r = ch >> 3, kc = (ch & 7) * 4;
            int n = n0 + r;
            bool ok = (n < N);
            uint32_t dst = (uint32_t)__cvta_generic_to_shared(&Bb[r * LDK + kc]);
            cp16(dst, &W[(size_t)(ok ? n : 0) * K + k0 + kc], ok);
        }
        cp_commit();
    };

    uint32_t aRow = (uint32_t)(wm * (BMt/2) + (lane & 15));
    uint32_t aColB = (lane >> 4) * 16;
    uint32_t aBaseOff = (aRow * LDK) * 4 + aColB;
    uint32_t bRow = (uint32_t)(wn * 64 + (lane & 7) + ((lane & 16) >> 1));
    uint32_t bColB = (lane & 8) * 2;
    uint32_t bBaseOff = (bRow * LDK) * 4 + bColB;

    int ntiles = K / BK;
    stage(0, 0);
    for (int i = 0; i < ntiles; i++) {
        if (i + 1 < ntiles) {
            stage((i + 1) & 1, (i + 1) * BK);
            asm volatile("cp.async.wait_group 1;\n" ::: "memory");
        } else {
            asm volatile("cp.async.wait_group 0;\n" ::: "memory");
        }
        __syncthreads();

        uint32_t sAb = (uint32_t)__cvta_generic_to_shared(As + (i & 1) * BMt * LDK);
        uint32_t sBb = (uint32_t)__cvta_generic_to_shared(Bs + (i & 1) * BN * LDK);
        uint32_t aAddr = sAb + aBaseOff;
        uint32_t bAddr = sBb + bBaseOff;

        #pragma unroll
        for (int kk = 0; kk < BK; kk += 8) {
            uint32_t af[MT][4];
            #pragma unroll
            for (int mt = 0; mt < MT; mt++)
                ldsm4(af[mt][0], af[mt][1], af[mt][2], af[mt][3],
                      aAddr + (uint32_t)(mt * 16 * LDK + kk) * 4);
            uint32_t bf[8][2];
            #pragma unroll
            for (int ntp = 0; ntp < 4; ntp++)
                ldsm4(bf[2*ntp][0], bf[2*ntp][1], bf[2*ntp+1][0], bf[2*ntp+1][1],
                      bAddr + (uint32_t)(ntp * 16 * LDK + kk) * 4);
            #pragma unroll
            for (int mt = 0; mt < MT; mt++)
                #pragma unroll
                for (int nt = 0; nt < 8; nt++) {
                    asm volatile(
                        "mma.sync.aligned.m16n8k8.row.col.f32.tf32.tf32.f32 "
                        "{%0,%1,%2,%3}, {%4,%5,%6,%7}, {%8,%9}, {%0,%1,%2,%3};"
                        : "+f"(acc[mt][nt][0]), "+f"(acc[mt][nt][1]),
                          "+f"(acc[mt][nt][2]), "+f"(acc[mt][nt][3])
                        : "r"(af[mt][0]), "r"(af[mt][1]), "r"(af[mt][2]), "r"(af[mt][3]),
                          "r"(bf[nt][0]), "r"(bf[nt][1]));
                }
        }
        __syncthreads();
    }

    int gg = lane >> 2, tt = lane & 3;
    #pragma unroll
    for (int mt = 0; mt < MT; mt++) {
        #pragma unroll
        for (int nt = 0; nt < 8; nt++) {
            int mbase = m0 + wm * (BMt/2) + mt * 16 + gg;
            int nn = n0 + wn * 64 + nt * 8 + 2 * tt;
            if (nn < N) {
                #pragma unroll
                for (int rhalf = 0; rhalf < 2; rhalf++) {
                    int mm = mbase + rhalf * 8;
                    float v0 = acc[mt][nt][rhalf*2 + 0];
                    float v1 = acc[mt][nt][rhalf*2 + 1];
                    if (EPI == 1) {
                        v0 += bias[nn];     v1 += bias[nn+1];
                        v0 = 0.5f * v0 * (1.f + erff(v0 * 0.70710678118654752f));
                        v1 = 0.5f * v1 * (1.f + erff(v1 * 0.70710678118654752f));
                        v0 = rnd_tf32(v0);  v1 = rnd_tf32(v1);
                    } else if (EPI == 2) {
                        float2 r = *(const float2*)&resid[(size_t)mm * N + nn];
                        v0 += r.x; v1 += r.y;
                    } else if (EPI == 3) {
                        float2 r = *(const float2*)&resid[(size_t)mm * N + nn];
                        v0 += bias[nn] + r.x; v1 += bias[nn+1] + r.y;
                    }
                    *(float2*)&C[(size_t)mm * N + nn] = make_float2(v0, v1);
                }
            }
        }
    }
}

// ---------------- chunked scan pass 1: fused conv(k=4)+silu + dt/dA + local scan ----------------
// grid = B*NH*NCHUNK blocks, 64 threads (one per p). Rolling 4-tap conv windows in registers.
__global__ void scan1_kernel(const float* __restrict__ zx, const float* __restrict__ cw,
                             const float* __restrict__ cb,
                             const float* __restrict__ dtb, const float* __restrict__ Alog,
                             const float* __restrict__ D_ssm,
                             float* __restrict__ y, float* __restrict__ bcout,
                             float* __restrict__ hfin,
                             float* __restrict__ cuma, float* __restrict__ P) {
    int blk = blockIdx.x;
    int c = blk % NCHUNK;
    int bh = blk / NCHUNK;
    int h = bh % NHQ, b = bh / NHQ;
    int p = threadIdx.x;
    int lane = p & 31;

    int chx  = h * HDQ + p;          // xBC channel (x part)
    int chbc = DIQ + lane;           // xBC channel (B/C part)
    int colx  = DIQ + chx;           // zx column of x channel
    int colbc = DIQ + chbc;          // zx column of B/C channel

    float cwx[DCONVQ], cwb[DCONVQ];
    #pragma unroll
    for (int j = 0; j < DCONVQ; j++) {
        cwx[j] = cw[chx*DCONVQ + j];
        cwb[j] = cw[chbc*DCONVQ + j];
    }
    float cbx = cb[chx], cbb = cb[chbc];

    float Dh = D_ssm[h];
    float dtbh = dtb[h];
    float eA = expf(Alog[h]);

    int l0 = c * CLEN;
    size_t rowbase = (size_t)b * LQ;

    // preload conv windows for l0-3 .. l0-1 (zeros before sequence start)
    float xw0=0.f, xw1=0.f, xw2=0.f, bw0=0.f, bw1=0.f, bw2=0.f;
    {
        int ll = l0 - 3;
        if (ll >= 0) { size_t r = rowbase + ll; xw0 = zx[r*DPROJQ + colx]; bw0 = zx[r*DPROJQ + colbc]; }
        ll = l0 - 2;
        if (ll >= 0) { size_t r = rowbase + ll; xw1 = zx[r*DPROJQ + colx]; bw1 = zx[r*DPROJQ + colbc]; }
        ll = l0 - 1;
        if (ll >= 0) { size_t r = rowbase + ll; xw2 = zx[r*DPROJQ + colx]; bw2 = zx[r*DPROJQ + colbc]; }
    }

    float hs[NSQ];
    #pragma unroll
    for (int n = 0; n < NSQ; n++) hs[n] = 0.f;
    float cum = 1.f;

    for (int l = l0; l < l0 + CLEN; l++) {
        size_t row = rowbase + l;
        float xn = zx[row*DPROJQ + colx];
        float bn = zx[row*DPROJQ + colbc];
        // conv: bias + taps in ascending j order (matches reference accumulation order)
        float accx = cbx;
        accx = fmaf(xw0, cwx[0], accx);
        accx = fmaf(xw1, cwx[1], accx);
        accx = fmaf(xw2, cwx[2], accx);
        accx = fmaf(xn,  cwx[3], accx);
        float accb = cbb;
        accb = fmaf(bw0, cwb[0], accb);
        accb = fmaf(bw1, cwb[1], accb);
        accb = fmaf(bw2, cwb[2], accb);
        accb = fmaf(bn,  cwb[3], accb);
        xw0 = xw1; xw1 = xw2; xw2 = xn;
        bw0 = bw1; bw1 = bw2; bw2 = bn;

        float xv  = accx / (1.f + expf(-accx));   // silu
        float bcv = accb / (1.f + expf(-accb));
        if (h == 0 && p < 32) bcout[row*(2*NSQ) + lane] = bcv;

        float raw = zx[row*DPROJQ + (DPROJQ - NHQ) + h] + dtbh;
        float dtv = (raw > 20.f) ? raw : log1pf(expf(raw));
        float a   = expf(-eA * dtv);
        cum *= a;
        if (p == 0) cuma[row*NHQ + h] = cum;

        float coef = dtv * xv;
        float acc = 0.f;
        #pragma unroll
        for (int n = 0; n < NSQ; n++) {
            float Bn = __shfl_sync(0xFFFFFFFFu, bcv, n);
            float Cn = __shfl_sync(0xFFFFFFFFu, bcv, 16 + n);
            hs[n] = fmaf(hs[n], a, coef * Bn);
            acc = fmaf(hs[n], Cn, acc);
        }
        y[row*DIQ + h*HDQ + p] = acc + Dh * xv;
    }
    size_t base = ((size_t)blk * HDQ + p) * NSQ;
    #pragma unroll
    for (int n = 0; n < NSQ; n++) hfin[base + n] = hs[n];
    if (p == 0) P[blk] = cum;
}

// ---------------- chunked scan pass 2 ----------------
__global__ void scan2_kernel(const float* __restrict__ hfin, const float* __restrict__ P,
                             float* __restrict__ hinit) {
    int bh = blockIdx.x;
    for (int e = threadIdx.x; e < HDQ*NSQ; e += 256) {
        float cur = 0.f;
        #pragma unroll 4
        for (int cc = 0; cc < NCHUNK; cc++) {
            size_t idx = (size_t)(bh * NCHUNK + cc) * (HDQ*NSQ) + e;
            hinit[idx] = cur;
            cur = P[bh * NCHUNK + cc] * cur + hfin[idx];
        }
    }
}

// ---------------- chunked scan pass 3 (reads compact BC buffer) ----------------
__global__ void scan3_kernel(const float* __restrict__ bc, const float* __restrict__ cuma,
                             const float* __restrict__ hinit, float* __restrict__ y) {
    int blk = blockIdx.x;
    int c = blk % NCHUNK;
    if (c == 0) return;
    int bh = blk / NCHUNK;
    int h = bh % NHQ, b = bh / NHQ;
    int p = threadIdx.x;
    int lane = p & 31;
    float hi[NSQ];
    size_t base = ((size_t)blk * HDQ + p) * NSQ;
    #pragma unroll
    for (int n = 0; n < NSQ; n++) hi[n] = hinit[base + n];
    int l0 = c * CLEN;
    for (int l = l0; l < l0 + CLEN; l++) {
        size_t row = (size_t)b * LQ + l;
        float bcv = bc[row*(2*NSQ) + lane];
        float ca  = cuma[row*NHQ + h];
        float corr = 0.f;
        #pragma unroll
        for (int n = 0; n < NSQ; n++)
            corr = fmaf(hi[n], __shfl_sync(0xFFFFFFFFu, bcv, 16 + n), corr);
        y[row*DIQ + h*HDQ + p] += ca * corr;
    }
}

// ---------------- gated RMSNorm over DI=1024 ----------------
__global__ void gate_norm_kernel(float* __restrict__ y, const float* __restrict__ zx,
                                 const float* __restrict__ gw) {
    __shared__ float sh[32];
    int m = blockIdx.x;
    int t = threadIdx.x;
    float v[4]; float ss = 0.f;
    #pragma unroll
    for (int i = 0; i < 4; i++) {
        int c = t + i*256;
        float z = zx[(size_t)m*DPROJQ + c];
        float yy = y[(size_t)m*DIQ + c];
        float g = z / (1.f + expf(-z));
        v[i] = yy * g;
        ss += v[i]*v[i];
    }
    float tot = block_reduce_sum(ss, sh);
    float scale = rsqrtf(tot * (1.f/DIQ) + EPSQ);
    #pragma unroll
    for (int i = 0; i < 4; i++) {
        int c = t + i*256;
        y[(size_t)m*DIQ + c] = rnd_tf32(v[i] * scale * gw[c]);
    }
}

// ---------------- launcher ----------------
extern "C" void kernel_launch(void* const* d_in, const int* in_sizes, int n_in,
                              void* d_out, int out_size) {
    const float* x          = (const float*)d_in[0];
    const float* in_proj_w  = (const float*)d_in[1];
    const float* conv_w     = (const float*)d_in[2];
    const float* conv_b     = (const float*)d_in[3];
    const float* dt_bias    = (const float*)d_in[4];
    const float* A_log      = (const float*)d_in[5];
    const float* D_ssm      = (const float*)d_in[6];
    const float* gnorm_w    = (const float*)d_in[7];
    const float* out_proj_w = (const float*)d_in[8];
    const float* ffn_w1     = (const float*)d_in[9];
    const float* ffn_b1     = (const float*)d_in[10];
    const float* ffn_w2     = (const float*)d_in[11];
    const float* ffn_b2     = (const float*)d_in[12];
    const float* norm_mamba = (const float*)d_in[13];
    const float* norm_ffn   = (const float*)d_in[14];
    const float* final_norm = (const float*)d_in[15];
    float* out = (float*)d_out;

    float *gx, *gxn, *gzx, *gbc, *gy, *gh1;
    float *ghfin, *ghinit, *gcuma, *gP, *gwip, *gwop, *gw1, *gw2;
    cudaGetSymbolAddress((void**)&gx,  g_x);
    cudaGetSymbolAddress((void**)&gxn, g_xn);
    cudaGetSymbolAddress((void**)&gzx, g_zx);
    cudaGetSymbolAddress((void**)&gbc, g_bc);
    cudaGetSymbolAddress((void**)&gy,  g_y);
    cudaGetSymbolAddress((void**)&gh1, g_h1);
    cudaGetSymbolAddress((void**)&ghfin, g_hfin);
    cudaGetSymbolAddress((void**)&ghinit,g_hinit);
    cudaGetSymbolAddress((void**)&gcuma, g_cuma);
    cudaGetSymbolAddress((void**)&gP,    g_P);
    cudaGetSymbolAddress((void**)&gwip,  g_wip);
    cudaGetSymbolAddress((void**)&gwop,  g_wop);
    cudaGetSymbolAddress((void**)&gw1,   g_w1);
    cudaGetSymbolAddress((void**)&gw2,   g_w2);

    const int smem128 = (2*128*LDK + 2*BN*LDK) * 4;
    const int smem64  = (2*64 *LDK + 2*BN*LDK) * 4;
    cudaFuncSetAttribute(gemm_tc4<0,128>, cudaFuncAttributeMaxDynamicSharedMemorySize, smem128);
    cudaFuncSetAttribute(gemm_tc4<1,128>, cudaFuncAttributeMaxDynamicSharedMemorySize, smem128);
    cudaFuncSetAttribute(gemm_tc4<2,64>,  cudaFuncAttributeMaxDynamicSharedMemorySize, smem64);
    cudaFuncSetAttribute(gemm_tc4<3,64>,  cudaFuncAttributeMaxDynamicSharedMemorySize, smem64);

    // pre-round all weights to tf32 bit patterns
    {
        int n;
        n = NLAYERSQ*DPROJQ*DMQ; cvt_tf32_kernel<<<(n/4+255)/256, 256>>>(in_proj_w,  gwip, n);
        n = NLAYERSQ*DMQ*DIQ;    cvt_tf32_kernel<<<(n/4+255)/256, 256>>>(out_proj_w, gwop, n);
        n = NLAYERSQ*DFFQ*DMQ;   cvt_tf32_kernel<<<(n/4+255)/256, 256>>>(ffn_w1,     gw1, n);
        n = NLAYERSQ*DMQ*DFFQ;   cvt_tf32_kernel<<<(n/4+255)/256, 256>>>(ffn_w2,     gw2, n);
    }

    for (int i = 0; i < NLAYERSQ; i++) {
        // --- mamba block ---
        if (i == 0) {
            rmsnorm_kernel<1><<<BLQ, 128>>>(x, norm_mamba, gxn, gx, 1);
        } else {
            rmsnorm_kernel<0><<<BLQ, 128>>>(gx, norm_mamba + i*DMQ, gxn, nullptr, 1);
        }

        gemm_tc4<0,128><<<dim3((DPROJQ+BN-1)/BN, BLQ/128), 128, smem128>>>(
            gxn, gwip + (size_t)i*DPROJQ*DMQ, gzx, nullptr, nullptr,
            BLQ, DPROJQ, DMQ);

        scan1_kernel<<<BQ*NHQ*NCHUNK, HDQ>>>(
            gzx, conv_w + (size_t)i*CONV_DIMQ*DCONVQ, conv_b + (size_t)i*CONV_DIMQ,
            dt_bias + i*NHQ, A_log + i*NHQ, D_ssm + i*NHQ,
            gy, gbc, ghfin, gcuma, gP);
        scan2_kernel<<<BQ*NHQ, 256>>>(ghfin, gP, ghinit);
        scan3_kernel<<<BQ*NHQ*NCHUNK, HDQ>>>(gbc, gcuma, ghinit, gy);

        gate_norm_kernel<<<BLQ, 256>>>(gy, gzx, gnorm_w + (size_t)i*DIQ);

        gemm_tc4<2,64><<<dim3(DMQ/BN, BLQ/64), 128, smem64>>>(
            gy, gwop + (size_t)i*DMQ*DIQ, gx, nullptr, gx,
            BLQ, DMQ, DIQ);

        // --- ffn block ---
        rmsnorm_kernel<0><<<BLQ, 128>>>(gx, norm_ffn + i*DMQ, gxn, nullptr, 1);

        gemm_tc4<1,128><<<dim3(DFFQ/BN, BLQ/128), 128, smem128>>>(
            gxn, gw1 + (size_t)i*DFFQ*DMQ, gh1, ffn_b1 + (size_t)i*DFFQ, nullptr,
            BLQ, DFFQ, DMQ);

        gemm_tc4<3,64><<<dim3(DMQ/BN, BLQ/64), 128, smem64>>>(
            gh1, gw2 + (size_t)i*DMQ*DFFQ, gx, ffn_b2 + (size_t)i*DMQ, gx,
            BLQ, DMQ, DFFQ);
    }

    rmsnorm_kernel<0><<<BLQ, 128>>>(gx, final_norm, out, nullptr, 0);
}